// round 14
// baseline (speedup 1.0000x reference)
#include <cuda_runtime.h>
#include <math.h>
#include <float.h>

#define N1 16384
#define N2 16384
#define G 128
#define GH (G + 2)                 // 130: 1-cell halo, no bounds checks in hot path
#define NCH (GH * GH)              // 16900
#define NCH4 16912                 // padded for int4 zeroing
#define CAPLOG 6
#define CAP (1 << CAPLOG)          // 64 slots (central cell lambda ~ 23, P(>64) ~ 1e-13)
#define BOX 6.0f
#define CS (2.0f * BOX / (float)G) // 0.09375
#define QNB 1024
#define QTPB 128                   // 4096 warps x 4 groups(8 lanes) = 16384 = N1
#define SNB 64
#define STPB 256

// Scratch (no allocations -> __device__ globals). Zero-init at load; block 0 of
// the query kernel re-zeros g_cnt/g_done each launch so graph replays are clean.
__device__ int          g_cnt[NCH4];
__device__ float2       g_pts[NCH * CAP];
__device__ float        g_bsum[QNB];
__device__ volatile unsigned int g_done;

__device__ __forceinline__ int cellcoord(float v) {
    int c = (int)floorf((v + BOX) * (1.0f / CS));
    return min(max(c, 0), G - 1) + 1;   // 1..G (interior of halo grid)
}

// Return-less increment -> REDG (no L2 round-trip funnel).
__device__ __forceinline__ void red_inc(volatile unsigned int* p) {
    asm volatile("red.global.gpu.add.u32 [%0], 1;" :: "l"((unsigned int*)p) : "memory");
}

// Scan a cell's points with 2-lane cooperation: lane parity `par` takes every
// other float4 (points interleave 2-per-float4), halving the serial load chain.
__device__ __forceinline__ void scan_cell_pair(int c, int par, float qx, float qy,
                                               float& lb2) {
    int n = min(__ldg(&g_cnt[c]), CAP);
    const float4* __restrict__ p = (const float4*)&g_pts[c << CAPLOG];
    for (int j = 2 * par; j < n; j += 4) {
        float4 v = __ldg(&p[j >> 1]);
        float dx0 = qx - v.x, dy0 = qy - v.y;
        lb2 = fminf(lb2, fmaf(dx0, dx0, dy0 * dy0));
        if (j + 1 < n) {
            float dx1 = qx - v.z, dy1 = qy - v.w;
            lb2 = fminf(lb2, fmaf(dx1, dx1, dy1 * dy1));
        }
    }
}

// Full-cell scan (used by the warp-wide tail path).
__device__ __forceinline__ void scan_cell_n(int c, int n, float qx, float qy,
                                            float& lb2) {
    const float4* __restrict__ p = (const float4*)&g_pts[c << CAPLOG];
    for (int j = 0; j < n; j += 2) {
        float4 v = __ldg(&p[j >> 1]);
        float dx0 = qx - v.x, dy0 = qy - v.y;
        lb2 = fminf(lb2, fmaf(dx0, dx0, dy0 * dy0));
        if (j + 1 < n) {
            float dx1 = qx - v.z, dy1 = qy - v.w;
            lb2 = fminf(lb2, fmaf(dx1, dx1, dy1 * dy1));
        }
    }
}

// ---- Kernel A: scatter pos2 into halo-grid buckets ----
__global__ void __launch_bounds__(STPB) scatter_kernel(const float* __restrict__ pos2) {
    int i = blockIdx.x * STPB + threadIdx.x;
    if (i < N2) {
        float2 p = ((const float2*)pos2)[i];
        int c = cellcoord(p.y) * GH + cellcoord(p.x);
        int slot = atomicAdd(&g_cnt[c], 1);
        if (slot < CAP) g_pts[(c << CAPLOG) + slot] = p;
    }
}

// ---- Kernel B: exact NN queries + reduction + state cleanup ----
__global__ void __launch_bounds__(QTPB) query_kernel(const float* __restrict__ pos1,
                                                     float* __restrict__ out) {
    const int lane = threadIdx.x & 31;
    const int s8   = lane & 7;                       // sub-lane in 8-lane group
    const int cell4 = s8 >> 1;                       // 0..3: cell of the 2x2
    const int par  = s8 & 1;                         // point-parity within cell
    const unsigned gmask = 0xFFu << (lane & 24);     // 8-lane group shuffle mask
    const unsigned FULL  = 0xFFFFFFFFu;
    const int wid = (blockIdx.x * QTPB + threadIdx.x) >> 5;

    // One query per 8-lane group: 4 per warp, exact cover of N1.
    const int q = wid * 4 + (lane >> 3);
    const float2 qp = ((const float2*)pos1)[q];
    const float qx = qp.x, qy = qp.y;

    // Cell coords + fractional position (exact 2x2 termination bound).
    const float tx = (qx + BOX) * (1.0f / CS);
    const float ty = (qy + BOX) * (1.0f / CS);
    const int cx = min(max((int)floorf(tx), 0), G - 1) + 1;
    const int cy = min(max((int)floorf(ty), 0), G - 1) + 1;
    const float fx = tx - floorf(tx);
    const float fy = ty - floorf(ty);
    const int ox = (fx >= 0.5f) ? 1 : -1;
    const int oy = (fy >= 0.5f) ? 1 : -1;
    const float mx = fmaxf(fx, 1.0f - fx);
    const float my = fmaxf(fy, 1.0f - fy);
    const float thr = CS * fminf(mx, my);            // dist q -> 2x2 block boundary
    const float thr2 = thr * thr;

    // Phase a: nearest 2x2 block; 2 lanes per cell, parity-split points.
    float best2 = FLT_MAX;
    {
        const int dx = (cell4 & 1) ? ox : 0;
        const int dy = (cell4 & 2) ? oy : 0;
        scan_cell_pair((cy + dy) * GH + (cx + dx), par, qx, qy, best2);
    }
    #pragma unroll
    for (int o = 4; o; o >>= 1)
        best2 = fminf(best2, __shfl_xor_sync(gmask, best2, o));

    // Phase b: escalate to full 3x3 if the 2x2 bound fails (rare).
    if (__any_sync(FULL, best2 > thr2)) {
        if (best2 > thr2) {
            // 5 remaining cells: t=0..2:(-ox,{-oy,0,oy}), t=3:(0,-oy), t=4:(ox,-oy)
            for (int t = cell4; t < 5; t += 4) {
                int dx = (t < 3) ? -ox : ((t == 3) ? 0 : ox);
                int dy = (t < 3) ? ((t - 1) * oy) : -oy;
                scan_cell_pair((cy + dy) * GH + (cx + dx), par, qx, qy, best2);
            }
        }
        #pragma unroll
        for (int o = 4; o; o >>= 1)
            best2 = fminf(best2, __shfl_xor_sync(gmask, best2, o));
    }

    // Phase c: rare tail — full-warp annulus expansion per pending query, with
    // MLP-4 count prefetch per 128-cell chunk. A point in ring r>=2 is at
    // distance >= (r-1)*CS; after scanning through ring r1, stop once
    // best2 <= (r1*CS)^2.
    {
        unsigned pend = __ballot_sync(FULL, (s8 == 0) && (best2 > CS * CS));
        while (pend) {
            const int src = __ffs(pend) - 1;
            pend &= pend - 1;
            const float wqx = __shfl_sync(FULL, qx, src);
            const float wqy = __shfl_sync(FULL, qy, src);
            const int   wcx = __shfl_sync(FULL, cx, src);
            const int   wcy = __shfl_sync(FULL, cy, src);
            float wb2 = __shfl_sync(FULL, best2, src);

            int r0 = 2;
            while (r0 < 2 * G) {
                const float dm = (float)(r0 - 1) * CS;
                if (wb2 <= dm * dm) break;
                const int r1 = r0 + 3;
                const int W  = 2 * r1 + 1;           // full-row width
                const int H  = r1 - r0 + 1;          // band thickness (=4)
                const int A  = 2 * H * W;            // top+bottom band cells
                const int w2 = 2 * H;
                const int ncells = A + (2 * r0 - 1) * w2;

                float lb2 = wb2;
                for (int tb = 0; tb < ncells; tb += 128) {
                    int cells[4];
                    int cnts[4];
                    // issue 4 independent count loads (MLP=4)
                    #pragma unroll
                    for (int k = 0; k < 4; k++) {
                        int t = tb + lane + 32 * k;
                        int idx = -1;
                        if (t < ncells) {
                            int dx, dy;
                            if (t < A) {
                                int row = t / W, col = t - row * W;
                                dy = (row < H) ? (-r1 + row) : (r0 + row - H);
                                dx = col - r1;
                            } else {
                                int u = t - A;
                                int row = u / w2, col = u - row * w2;
                                dy = -r0 + 1 + row;
                                dx = (col < H) ? (-r1 + col) : (r0 + col - H);
                            }
                            int xx = wcx + dx, yy = wcy + dy;
                            if (xx >= 1 && xx <= G && yy >= 1 && yy <= G)
                                idx = yy * GH + xx;
                        }
                        cells[k] = idx;
                        cnts[k] = (idx >= 0) ? min(__ldg(&g_cnt[idx]), CAP) : 0;
                    }
                    #pragma unroll
                    for (int k = 0; k < 4; k++)
                        if (cnts[k] > 0)
                            scan_cell_n(cells[k], cnts[k], wqx, wqy, lb2);
                }
                #pragma unroll
                for (int o = 16; o; o >>= 1)
                    lb2 = fminf(lb2, __shfl_xor_sync(FULL, lb2, o));
                wb2 = lb2;
                r0 = r1 + 1;
            }
            if (lane == src) best2 = wb2;
        }
    }

    // Warp-level deterministic sum (one contribution per query).
    float v = (s8 == 0) ? sqrtf(best2) : 0.0f;
    #pragma unroll
    for (int o = 16; o; o >>= 1)
        v += __shfl_xor_sync(FULL, v, o);             // fixed-order butterfly

    __shared__ float wsum[QTPB / 32];
    if (lane == 0) wsum[threadIdx.x >> 5] = v;
    __syncthreads();

    // Publish partial; detect completion via REDG + single poller in block 0.
    if (threadIdx.x == 0) {
        float bs = 0.0f;
        #pragma unroll
        for (int w = 0; w < QTPB / 32; w++) bs += wsum[w];
        g_bsum[blockIdx.x] = bs;
        __threadfence();
        red_inc(&g_done);
    }

    if (blockIdx.x != 0) return;

    // Block 0: wait for all partials, final fixed-order sum, state cleanup.
    if (threadIdx.x == 0) {
        while (g_done < (unsigned int)QNB) __nanosleep(64);
        __threadfence();
    }
    __syncthreads();

    __shared__ float fr[QTPB];
    {
        float acc = 0.0f;
        #pragma unroll
        for (int w = 0; w < QNB / QTPB; w++)
            acc += g_bsum[threadIdx.x + w * QTPB];
        fr[threadIdx.x] = acc;
    }
    __syncthreads();
    #pragma unroll
    for (int st = QTPB / 2; st > 0; st >>= 1) {
        if (threadIdx.x < st) fr[threadIdx.x] += fr[threadIdx.x + st];
        __syncthreads();
    }
    if (threadIdx.x == 0) {
        out[0] = fr[0] * (1.0f / (float)N1);
        g_done = 0;
    }
    // re-zero cell counters for the next graph replay
    int4* z = (int4*)g_cnt;
    for (int i = threadIdx.x; i < NCH4 / 4; i += QTPB)
        z[i] = make_int4(0, 0, 0, 0);
}

extern "C" void kernel_launch(void* const* d_in, const int* in_sizes, int n_in,
                              void* d_out, int out_size) {
    const float* pos1 = (const float*)d_in[0];
    const float* pos2 = (const float*)d_in[1];

    scatter_kernel<<<SNB, STPB>>>(pos2);
    query_kernel<<<QNB, QTPB>>>(pos1, (float*)d_out);
}

// round 15
// speedup vs baseline: 1.0763x; 1.0763x over previous
#include <cuda_runtime.h>
#include <math.h>
#include <float.h>

#define N1 16384
#define N2 16384
#define G 128
#define GH (G + 2)                 // 130: 1-cell halo, no bounds checks in hot path
#define NCH (GH * GH)              // 16900
#define NCH4 16912                 // padded for int4 zeroing
#define CAPLOG 6
#define CAP (1 << CAPLOG)          // 64 slots (central cell lambda ~ 23, P(>64) ~ 1e-13)
#define BOX 6.0f
#define CS (2.0f * BOX / (float)G) // 0.09375
#define QNB 1024
#define QTPB 128                   // 4096 warps x 4 groups(8 lanes) = 16384 = N1
#define SNB 64
#define STPB 256

// Scratch (no allocations -> __device__ globals). Zero-init at load; block 0 of
// the query kernel re-zeros g_cnt/g_done each launch so graph replays are clean.
__device__ int          g_cnt[NCH4];
__device__ float2       g_pts[NCH * CAP];
__device__ float        g_bsum[QNB];
__device__ volatile unsigned int g_done;

__device__ __forceinline__ int cellcoord(float v) {
    int c = (int)floorf((v + BOX) * (1.0f / CS));
    return min(max(c, 0), G - 1) + 1;   // 1..G (interior of halo grid)
}

__device__ __forceinline__ void red_inc(volatile unsigned int* p) {
    asm volatile("red.global.gpu.add.u32 [%0], 1;" :: "l"((unsigned int*)p) : "memory");
}

// Full-cell scan (tail path only).
__device__ __forceinline__ void scan_cell_n(int c, int n, float qx, float qy,
                                            float& lb2) {
    const float4* __restrict__ p = (const float4*)&g_pts[c << CAPLOG];
    for (int j = 0; j < n; j += 2) {
        float4 v = __ldg(&p[j >> 1]);
        float dx0 = qx - v.x, dy0 = qy - v.y;
        lb2 = fminf(lb2, fmaf(dx0, dx0, dy0 * dy0));
        if (j + 1 < n) {
            float dx1 = qx - v.z, dy1 = qy - v.w;
            lb2 = fminf(lb2, fmaf(dx1, dx1, dy1 * dy1));
        }
    }
}

// ---- Kernel A: scatter pos2 into halo-grid buckets ----
__global__ void __launch_bounds__(STPB) scatter_kernel(const float* __restrict__ pos2) {
    int i = blockIdx.x * STPB + threadIdx.x;
    if (i < N2) {
        float2 p = ((const float2*)pos2)[i];
        int c = cellcoord(p.y) * GH + cellcoord(p.x);
        int slot = atomicAdd(&g_cnt[c], 1);
        if (slot < CAP) g_pts[(c << CAPLOG) + slot] = p;
    }
}

// ---- Kernel B: exact NN queries + reduction + state cleanup ----
__global__ void __launch_bounds__(QTPB) query_kernel(const float* __restrict__ pos1,
                                                     float* __restrict__ out) {
    const int lane = threadIdx.x & 31;
    const int s8   = lane & 7;                       // sub-lane in 8-lane group
    const int gb   = lane & 24;                      // group base lane
    const unsigned FULL = 0xFFFFFFFFu;
    const int wid = (blockIdx.x * QTPB + threadIdx.x) >> 5;

    // One query per 8-lane group: 4 per warp, exact cover of N1.
    const int q = wid * 4 + (lane >> 3);
    const float2 qp = ((const float2*)pos1)[q];
    const float qx = qp.x, qy = qp.y;

    const float tx = (qx + BOX) * (1.0f / CS);
    const float ty = (qy + BOX) * (1.0f / CS);
    const int cx = min(max((int)floorf(tx), 0), G - 1) + 1;
    const int cy = min(max((int)floorf(ty), 0), G - 1) + 1;
    const float fx = tx - floorf(tx);
    const float fy = ty - floorf(ty);
    const int ox = (fx >= 0.5f) ? 1 : -1;
    const int oy = (fy >= 0.5f) ? 1 : -1;
    const float mx = fmaxf(fx, 1.0f - fx);
    const float my = fmaxf(fy, 1.0f - fy);
    const float thr = CS * fminf(mx, my);            // dist q -> 2x2 block boundary
    const float thr2 = thr * thr;

    // ---- Phase a: nearest 2x2 block, concatenated balanced scan ----
    // Cell addresses of the 2x2 block (halo makes all of them safe).
    const int a0 = cy * GH + cx;
    const int a1 = a0 + ox;
    const int a2 = a0 + oy * GH;
    const int a3 = a2 + ox;

    // One count load per lane (lanes 0-3 of the group), broadcast via shuffle.
    int myaddr = (s8 == 1) ? a1 : (s8 == 2) ? a2 : (s8 == 3) ? a3 : a0;
    int nk = (s8 < 4) ? min(__ldg(&g_cnt[myaddr]), CAP) : 0;
    const int n0 = __shfl_sync(FULL, nk, gb + 0);
    const int n1 = __shfl_sync(FULL, nk, gb + 1);
    const int n2 = __shfl_sync(FULL, nk, gb + 2);
    const int n3 = __shfl_sync(FULL, nk, gb + 3);
    // float4-unit prefix offsets of the concatenated point list.
    const int o1 = (n0 + 1) >> 1;
    const int o2 = o1 + ((n1 + 1) >> 1);
    const int o3 = o2 + ((n2 + 1) >> 1);
    const int tot = o3 + ((n3 + 1) >> 1);

    float best2 = FLT_MAX;
    {
        // 6 unrolled predicated iterations (covers 96 points) + rare spill loop.
        #pragma unroll
        for (int i = 0; i < 6; i++) {
            int t = s8 + 8 * i;
            if (t < tot) {
                int c   = (t >= o1) + (t >= o2) + (t >= o3);
                int off = (c == 0) ? 0  : (c == 1) ? o1 : (c == 2) ? o2 : o3;
                int ad  = (c == 0) ? a0 : (c == 1) ? a1 : (c == 2) ? a2 : a3;
                int nc  = (c == 0) ? n0 : (c == 1) ? n1 : (c == 2) ? n2 : n3;
                int fj  = t - off;
                float4 v = __ldg(((const float4*)&g_pts[ad << CAPLOG]) + fj);
                float dx0 = qx - v.x, dy0 = qy - v.y;
                best2 = fminf(best2, fmaf(dx0, dx0, dy0 * dy0));
                if (2 * fj + 1 < nc) {
                    float dx1 = qx - v.z, dy1 = qy - v.w;
                    best2 = fminf(best2, fmaf(dx1, dx1, dy1 * dy1));
                }
            }
        }
        for (int t = s8 + 48; t < tot; t += 8) {
            int c   = (t >= o1) + (t >= o2) + (t >= o3);
            int off = (c == 0) ? 0  : (c == 1) ? o1 : (c == 2) ? o2 : o3;
            int ad  = (c == 0) ? a0 : (c == 1) ? a1 : (c == 2) ? a2 : a3;
            int nc  = (c == 0) ? n0 : (c == 1) ? n1 : (c == 2) ? n2 : n3;
            int fj  = t - off;
            float4 v = __ldg(((const float4*)&g_pts[ad << CAPLOG]) + fj);
            float dx0 = qx - v.x, dy0 = qy - v.y;
            best2 = fminf(best2, fmaf(dx0, dx0, dy0 * dy0));
            if (2 * fj + 1 < nc) {
                float dx1 = qx - v.z, dy1 = qy - v.w;
                best2 = fminf(best2, fmaf(dx1, dx1, dy1 * dy1));
            }
        }
    }
    #pragma unroll
    for (int o = 4; o; o >>= 1)
        best2 = fminf(best2, __shfl_xor_sync(FULL, best2, o));   // stays in group

    // ---- Phase b: escalate to remaining 5 cells of the 3x3 (rare) ----
    bool esc = best2 > thr2;                          // group-uniform
    if (__any_sync(FULL, esc)) {
        const int b0 = (cy - oy) * GH + (cx - ox);
        const int b1 =  cy       * GH + (cx - ox);
        const int b2 = (cy + oy) * GH + (cx - ox);
        const int b3 = (cy - oy) * GH +  cx;
        const int b4 = (cy - oy) * GH + (cx + ox);

        int baddr = (s8 == 1) ? b1 : (s8 == 2) ? b2 : (s8 == 3) ? b3 :
                    (s8 == 4) ? b4 : b0;
        int mb = (esc && s8 < 5) ? min(__ldg(&g_cnt[baddr]), CAP) : 0;
        const int m0 = __shfl_sync(FULL, mb, gb + 0);
        const int m1 = __shfl_sync(FULL, mb, gb + 1);
        const int m2 = __shfl_sync(FULL, mb, gb + 2);
        const int m3 = __shfl_sync(FULL, mb, gb + 3);
        const int m4 = __shfl_sync(FULL, mb, gb + 4);
        const int p1 = (m0 + 1) >> 1;
        const int p2 = p1 + ((m1 + 1) >> 1);
        const int p3 = p2 + ((m2 + 1) >> 1);
        const int p4 = p3 + ((m3 + 1) >> 1);
        const int btot = p4 + ((m4 + 1) >> 1);

        if (esc) {
            for (int t = s8; t < btot; t += 8) {
                int c   = (t >= p1) + (t >= p2) + (t >= p3) + (t >= p4);
                int off = (c == 0) ? 0  : (c == 1) ? p1 : (c == 2) ? p2 :
                          (c == 3) ? p3 : p4;
                int ad  = (c == 0) ? b0 : (c == 1) ? b1 : (c == 2) ? b2 :
                          (c == 3) ? b3 : b4;
                int nc  = (c == 0) ? m0 : (c == 1) ? m1 : (c == 2) ? m2 :
                          (c == 3) ? m3 : m4;
                int fj  = t - off;
                float4 v = __ldg(((const float4*)&g_pts[ad << CAPLOG]) + fj);
                float dx0 = qx - v.x, dy0 = qy - v.y;
                best2 = fminf(best2, fmaf(dx0, dx0, dy0 * dy0));
                if (2 * fj + 1 < nc) {
                    float dx1 = qx - v.z, dy1 = qy - v.w;
                    best2 = fminf(best2, fmaf(dx1, dx1, dy1 * dy1));
                }
            }
        }
        #pragma unroll
        for (int o = 4; o; o >>= 1)
            best2 = fminf(best2, __shfl_xor_sync(FULL, best2, o));
    }

    // ---- Phase c: rare tail — full-warp annulus expansion per pending query,
    // MLP-4 count prefetch per 128-cell chunk. A point in ring r>=2 is at
    // distance >= (r-1)*CS; after scanning through ring r1, stop once
    // best2 <= (r1*CS)^2.
    {
        unsigned pend = __ballot_sync(FULL, (s8 == 0) && (best2 > CS * CS));
        while (pend) {
            const int src = __ffs(pend) - 1;
            pend &= pend - 1;
            const float wqx = __shfl_sync(FULL, qx, src);
            const float wqy = __shfl_sync(FULL, qy, src);
            const int   wcx = __shfl_sync(FULL, cx, src);
            const int   wcy = __shfl_sync(FULL, cy, src);
            float wb2 = __shfl_sync(FULL, best2, src);

            int r0 = 2;
            while (r0 < 2 * G) {
                const float dm = (float)(r0 - 1) * CS;
                if (wb2 <= dm * dm) break;
                const int r1 = r0 + 3;
                const int W  = 2 * r1 + 1;
                const int H  = r1 - r0 + 1;
                const int A  = 2 * H * W;
                const int w2 = 2 * H;
                const int ncells = A + (2 * r0 - 1) * w2;

                float lb2 = wb2;
                for (int tb = 0; tb < ncells; tb += 128) {
                    int cells[4];
                    int cnts[4];
                    #pragma unroll
                    for (int k = 0; k < 4; k++) {
                        int t = tb + lane + 32 * k;
                        int idx = -1;
                        if (t < ncells) {
                            int dx, dy;
                            if (t < A) {
                                int row = t / W, col = t - row * W;
                                dy = (row < H) ? (-r1 + row) : (r0 + row - H);
                                dx = col - r1;
                            } else {
                                int u = t - A;
                                int row = u / w2, col = u - row * w2;
                                dy = -r0 + 1 + row;
                                dx = (col < H) ? (-r1 + col) : (r0 + col - H);
                            }
                            int xx = wcx + dx, yy = wcy + dy;
                            if (xx >= 1 && xx <= G && yy >= 1 && yy <= G)
                                idx = yy * GH + xx;
                        }
                        cells[k] = idx;
                        cnts[k] = (idx >= 0) ? min(__ldg(&g_cnt[idx]), CAP) : 0;
                    }
                    #pragma unroll
                    for (int k = 0; k < 4; k++)
                        if (cnts[k] > 0)
                            scan_cell_n(cells[k], cnts[k], wqx, wqy, lb2);
                }
                #pragma unroll
                for (int o = 16; o; o >>= 1)
                    lb2 = fminf(lb2, __shfl_xor_sync(FULL, lb2, o));
                wb2 = lb2;
                r0 = r1 + 1;
            }
            if (lane == src) best2 = wb2;
        }
    }

    // ---- Warp-level deterministic sum (one contribution per query) ----
    float v = (s8 == 0) ? sqrtf(best2) : 0.0f;
    #pragma unroll
    for (int o = 16; o; o >>= 1)
        v += __shfl_xor_sync(FULL, v, o);             // fixed-order butterfly

    __shared__ float wsum[QTPB / 32];
    if (lane == 0) wsum[threadIdx.x >> 5] = v;
    __syncthreads();

    if (threadIdx.x == 0) {
        float bs = 0.0f;
        #pragma unroll
        for (int w = 0; w < QTPB / 32; w++) bs += wsum[w];
        g_bsum[blockIdx.x] = bs;
        __threadfence();
        red_inc(&g_done);
    }

    if (blockIdx.x != 0) return;

    // Block 0: wait for all partials, final fixed-order sum, state cleanup.
    if (threadIdx.x == 0) {
        while (g_done < (unsigned int)QNB) __nanosleep(64);
        __threadfence();
    }
    __syncthreads();

    __shared__ float fr[QTPB];
    {
        float acc = 0.0f;
        #pragma unroll
        for (int w = 0; w < QNB / QTPB; w++)
            acc += g_bsum[threadIdx.x + w * QTPB];
        fr[threadIdx.x] = acc;
    }
    __syncthreads();
    #pragma unroll
    for (int st = QTPB / 2; st > 0; st >>= 1) {
        if (threadIdx.x < st) fr[threadIdx.x] += fr[threadIdx.x + st];
        __syncthreads();
    }
    if (threadIdx.x == 0) {
        out[0] = fr[0] * (1.0f / (float)N1);
        g_done = 0;
    }
    int4* z = (int4*)g_cnt;
    for (int i = threadIdx.x; i < NCH4 / 4; i += QTPB)
        z[i] = make_int4(0, 0, 0, 0);
}

extern "C" void kernel_launch(void* const* d_in, const int* in_sizes, int n_in,
                              void* d_out, int out_size) {
    const float* pos1 = (const float*)d_in[0];
    const float* pos2 = (const float*)d_in[1];

    scatter_kernel<<<SNB, STPB>>>(pos2);
    query_kernel<<<QNB, QTPB>>>(pos1, (float*)d_out);
}